// round 14
// baseline (speedup 1.0000x reference)
#include <cuda_runtime.h>
#include <cstddef>

// Problem constants (fixed by setup_inputs)
#define B_   2
#define CV   64
#define CR   20
#define E_   64
#define CO   64
#define MV   100000
#define MR   50000
#define NV   262144      // v2p count per batch
#define NN   65536       // bundles per batch (N / bundle, bundle = 4)
#define TOTN (B_ * NN)   // 131072
#define CELLS (B_ * MR)  // 100000

typedef unsigned long long ull;

// ---------------- scratch (device globals: allocation-free, 16B-aligned) ----------------
__device__ __align__(16) float g_vT[(size_t)B_ * MV * CV];    // v_feat^T: (B, Mv, 64)
__device__ __align__(16) float g_qd[(size_t)CELLS * 64];      // dense q per cell
__device__ __align__(16) float g_vbar[(size_t)CELLS * 64];    // per-cell summed vbar (RED)
__device__ __align__(16) float g_WovT[64 * 64];               // [f][o]
__device__ int   g_iv[(size_t)B_ * NV];                       // v indices (int32)
__device__ int   g_ir[(size_t)TOTN];                          // r indices (int32)

__device__ __forceinline__ bool detect_int64(const int* __restrict__ p) {
    bool i64 = true;
#pragma unroll
    for (int i = 1; i < 32; i += 2) i64 &= (p[i] == 0);
    return i64;
}

// ---------------- phase1: vT transpose + repack + zero + Wov fold + qd GEMM ----------------
#define TR_BX ((MV + 63) / 64)           // 1563
#define TR_BLKS (TR_BX * B_)             // 3126
#define RP_BLKS 256
#define ZR_BLKS 128
#define WOV_BLKS 2
#define QD_TILE 128
#define QD_PAD 134
#define QD_BX ((MR + QD_TILE - 1) / QD_TILE)   // 391
#define QD_BLKS (QD_BX * B_)                   // 782
#define P1_GRID (TR_BLKS + RP_BLKS + ZR_BLKS + WOV_BLKS + QD_BLKS)

// shared buffer sized for the qd region (largest): Wk 4096 + Wq 1280 + sW 1280 + sR 20*134
#define SB_WK  0
#define SB_WQ  4096
#define SB_SW  5376
#define SB_SR  6656
#define SB_FLOATS (SB_SR + CR * QD_PAD)   // 9336 floats ~= 37.3 KB

__global__ __launch_bounds__(256) void phase1_kernel(
    const float* __restrict__ v_feat, const float* __restrict__ r_feat,
    const void* __restrict__ v2p, const void* __restrict__ r2p,
    const float* __restrict__ Wq, const float* __restrict__ Wk,
    const float* __restrict__ Wv, const float* __restrict__ Wo) {
    __shared__ float sbuf[SB_FLOATS];

    int blk = blockIdx.x;
    int tid = threadIdx.x;

    if (blk < TR_BLKS) {
        // ---- v transpose: (B, 64, Mv) -> (B, Mv, 64), float4 both sides ----
        float (*tile)[65] = (float (*)[65])sbuf;   // [m_local][c]
        int bx = blk % TR_BX;
        int b = blk / TR_BX;
        int m0 = bx * 64;
        const float* inb = v_feat + (size_t)b * CV * MV;
        float* outb = g_vT + (size_t)b * MV * CV;

#pragma unroll
        for (int j = 0; j < 4; j++) {
            int idx = tid + j * 256;
            int c = idx >> 4;
            int mq = idx & 15;
            int m = m0 + mq * 4;
            if (m < MV) {   // MV % 4 == 0
                float4 v = *(const float4*)(inb + (size_t)c * MV + m);
                tile[mq * 4 + 0][c] = v.x;
                tile[mq * 4 + 1][c] = v.y;
                tile[mq * 4 + 2][c] = v.z;
                tile[mq * 4 + 3][c] = v.w;
            }
        }
        __syncthreads();
#pragma unroll
        for (int j = 0; j < 4; j++) {
            int idx = tid + j * 256;
            int ml = idx >> 4;
            int cq = idx & 15;
            int m = m0 + ml;
            if (m < MV) {
                float4 v = make_float4(tile[ml][cq * 4 + 0], tile[ml][cq * 4 + 1],
                                       tile[ml][cq * 4 + 2], tile[ml][cq * 4 + 3]);
                *(float4*)(outb + (size_t)m * CV + cq * 4) = v;
            }
        }
    } else if (blk < TR_BLKS + RP_BLKS) {
        // ---- index repack (int32 or int64 source) ----
        const int* pv = (const int*)v2p;
        const int* pr = (const int*)r2p;
        bool v64 = detect_int64(pv);
        bool r64 = detect_int64(pr);
        int t = (blk - TR_BLKS) * 256 + tid;
        int stride = RP_BLKS * 256;
        for (int i = t; i < B_ * NV; i += stride)
            g_iv[i] = v64 ? pv[(size_t)4 * i] : pv[(size_t)2 * i];
        for (int i = t; i < TOTN; i += stride)
            g_ir[i] = r64 ? pr[(size_t)4 * i] : pr[(size_t)2 * i];
    } else if (blk < TR_BLKS + RP_BLKS + ZR_BLKS) {
        // ---- zero RED accumulator ----
        float4* p = (float4*)g_vbar;
        int n4 = (CELLS * 64) / 4;
        int t = (blk - TR_BLKS - RP_BLKS) * 256 + tid;
        int stride = ZR_BLKS * 256;
        float4 z = make_float4(0.f, 0.f, 0.f, 0.f);
        for (int i = t; i < n4; i += stride) p[i] = z;
    } else if (blk < TR_BLKS + RP_BLKS + ZR_BLKS + WOV_BLKS) {
        // ---- Wov fold (2 blocks) ----
        int half = blk - (TR_BLKS + RP_BLKS + ZR_BLKS);  // 0 or 1
        float* sA = sbuf;             // Wv 64x64
        float* sB = sbuf + 4096;      // Wo 64x64
        for (int i = tid; i < 64 * 64; i += 256) sA[i] = Wv[i];
        for (int i = tid; i < 64 * 64; i += 256) sB[i] = Wo[i];
        __syncthreads();
        for (int ii = half * 2048 + tid; ii < half * 2048 + 2048; ii += 256) {
            int f = ii >> 6, o = ii & 63;
            float s = 0.f;
#pragma unroll
            for (int e = 0; e < 64; e++) s += sB[o * 64 + e] * sA[e * 64 + f];
            g_WovT[ii] = s;  // [f][o]
        }
    } else {
        // ---- qd GEMM: g_qd[b][m][f] = sum_c r_feat[b][c][m] * Wkq[c][f] ----
        float* sWk = sbuf + SB_WK;   // [e][f] 64x64
        float* sWq = sbuf + SB_WQ;   // [e][c] 64x20
        float* sW  = sbuf + SB_SW;   // [c][f] 20x64
        float* sR  = sbuf + SB_SR;   // [c][m-local] 20x134

        int qblk = blk - (TR_BLKS + RP_BLKS + ZR_BLKS + WOV_BLKS);
        int b = qblk / QD_BX;
        int m0 = (qblk % QD_BX) * QD_TILE;

        for (int i = tid; i < 64 * 64; i += 256) sWk[i] = Wk[i];
        for (int i = tid; i < 64 * CR; i += 256) sWq[i] = Wq[i];
        for (int i = tid; i < CR * QD_TILE; i += 256) {
            int c = i / QD_TILE;
            int m = i - c * QD_TILE;
            float v = 0.f;
            if (m0 + m < MR) v = r_feat[((size_t)b * CR + c) * MR + m0 + m];
            sR[c * QD_PAD + m] = v;
        }
        __syncthreads();
        // fold Wkq into sW
        for (int i = tid; i < CR * 64; i += 256) {
            int c = i >> 6, f = i & 63;
            float s = 0.f;
#pragma unroll
            for (int e = 0; e < 64; e++) s += sWk[e * 64 + f] * sWq[e * CR + c];
            sW[c * 64 + f] = s;
        }
        __syncthreads();

        int f0 = (tid & 7) * 8;
        int ml0 = (tid >> 3) * 4;

        ull acc2[4][4];   // p = f-pair, j = m
#pragma unroll
        for (int p = 0; p < 4; p++)
#pragma unroll
            for (int j = 0; j < 4; j++) acc2[p][j] = 0ull;

#pragma unroll
        for (int c = 0; c < CR; c++) {
            const float* wrow = sW + c * 64 + f0;
            ull w2[4];
#pragma unroll
            for (int p = 0; p < 4; p++) w2[p] = *(const ull*)(wrow + 2 * p);
            const float* vrow = sR + c * QD_PAD + ml0;
            ull v2[4];
#pragma unroll
            for (int j = 0; j < 4; j++) {
                float vj = vrow[j];
                asm("mov.b64 %0, {%1, %1};" : "=l"(v2[j]) : "f"(vj));
            }
#pragma unroll
            for (int p = 0; p < 4; p++)
#pragma unroll
                for (int j = 0; j < 4; j++)
                    asm("fma.rn.f32x2 %0, %1, %2, %0;"
                        : "+l"(acc2[p][j]) : "l"(w2[p]), "l"(v2[j]));
        }

#pragma unroll
        for (int j = 0; j < 4; j++) {
            int m = m0 + ml0 + j;
            if (m < MR) {
                float a[8];
#pragma unroll
                for (int p = 0; p < 4; p++)
                    asm("mov.b64 {%0, %1}, %2;" : "=f"(a[2 * p]), "=f"(a[2 * p + 1])
                        : "l"(acc2[p][j]));
                float* dst = g_qd + ((size_t)b * MR + m) * 64 + f0;
                *(float4*)dst = make_float4(a[0], a[1], a[2], a[3]);
                *(float4*)(dst + 4) = make_float4(a[4], a[5], a[6], a[7]);
            }
        }
    }
}

// ---------------- attention: gather q + v (batched loads), softmax, RED into g_vbar ----------------
__global__ __launch_bounds__(256) void attn_kernel() {
    const unsigned FULL = 0xffffffffu;
    int gw = (blockIdx.x * 256 + threadIdx.x) >> 5;  // warp id, 4 bundles each
    int lane = threadIdx.x & 31;
    int sub = lane >> 3;
    int fl = lane & 7;

    int n = gw * 4 + sub;
    int b = n >> 16;

    int ldv = 0;
    if (lane < 16) ldv = g_iv[(size_t)gw * 16 + lane];
    else if (lane < 20) ldv = g_ir[gw * 4 + (lane - 16)];

    int ir_n = __shfl_sync(FULL, ldv, 16 + sub);
    int ivm[4];
#pragma unroll
    for (int m = 0; m < 4; m++) ivm[m] = __shfl_sync(FULL, ldv, sub * 4 + m);

    const float4* qp = (const float4*)(g_qd + ((size_t)b * MR + ir_n) * 64 + fl * 8);
    float4 q0 = qp[0];
    float4 q1 = qp[1];

    const float* vbase = g_vT + (size_t)b * MV * 64;
    float4 v0[4], v1[4];
#pragma unroll
    for (int m = 0; m < 4; m++) {
        const float4* vp = (const float4*)(vbase + (size_t)ivm[m] * 64 + fl * 8);
        v0[m] = vp[0];
        v1[m] = vp[1];
    }

    float s[4];
#pragma unroll
    for (int m = 0; m < 4; m++) {
        float p = q0.x * v0[m].x + q0.y * v0[m].y + q0.z * v0[m].z + q0.w * v0[m].w
                + q1.x * v1[m].x + q1.y * v1[m].y + q1.z * v1[m].z + q1.w * v1[m].w;
        p += __shfl_xor_sync(FULL, p, 4);
        p += __shfl_xor_sync(FULL, p, 2);
        p += __shfl_xor_sync(FULL, p, 1);
        s[m] = p * 0.125f;  // 1/sqrt(E=64)
    }

    float mx = fmaxf(fmaxf(s[0], s[1]), fmaxf(s[2], s[3]));
    float e0 = __expf(s[0] - mx), e1 = __expf(s[1] - mx);
    float e2 = __expf(s[2] - mx), e3 = __expf(s[3] - mx);
    float inv = 1.0f / (e0 + e1 + e2 + e3);
    e0 *= inv; e1 *= inv; e2 *= inv; e3 *= inv;

    float4 o0, o1;
    o0.x = e0 * v0[0].x + e1 * v0[1].x + e2 * v0[2].x + e3 * v0[3].x;
    o0.y = e0 * v0[0].y + e1 * v0[1].y + e2 * v0[2].y + e3 * v0[3].y;
    o0.z = e0 * v0[0].z + e1 * v0[1].z + e2 * v0[2].z + e3 * v0[3].z;
    o0.w = e0 * v0[0].w + e1 * v0[1].w + e2 * v0[2].w + e3 * v0[3].w;
    o1.x = e0 * v1[0].x + e1 * v1[1].x + e2 * v1[2].x + e3 * v1[3].x;
    o1.y = e0 * v1[0].y + e1 * v1[1].y + e2 * v1[2].y + e3 * v1[3].y;
    o1.z = e0 * v1[0].z + e1 * v1[1].z + e2 * v1[2].z + e3 * v1[3].z;
    o1.w = e0 * v1[0].w + e1 * v1[1].w + e2 * v1[2].w + e3 * v1[3].w;

    float* dst = g_vbar + ((size_t)b * MR + ir_n) * 64 + fl * 8;
    asm volatile("red.global.add.v4.f32 [%0], {%1, %2, %3, %4};"
                 :: "l"(dst), "f"(o0.x), "f"(o0.y), "f"(o0.z), "f"(o0.w) : "memory");
    asm volatile("red.global.add.v4.f32 [%0], {%1, %2, %3, %4};"
                 :: "l"(dst + 4), "f"(o1.x), "f"(o1.y), "f"(o1.z), "f"(o1.w) : "memory");
}

// ---------------- dense output GEMM: out[b][o][m] = sum_f Wov[f][o] * vbar[m][f] ----------------
// warp-broadcast W via uniform-address __ldg (L1-resident), sVT only in smem (~34 KB)
#define OTILE 128
#define OPAD 134
#define OUT3_FLOATS (64 * OPAD)
#define OUT3_BYTES  (OUT3_FLOATS * 4)

__global__ __launch_bounds__(256) void out3_kernel(float* __restrict__ out) {
    extern __shared__ float sVT[];   // [f][cl]

    int tid = threadIdx.x;
    int b = blockIdx.y;
    int m0 = blockIdx.x * OTILE;

    for (int i = tid; i < OTILE * 16; i += 256) {
        int cl = i >> 4;
        int c4 = i & 15;
        int m = m0 + cl;
        float4 v = make_float4(0.f, 0.f, 0.f, 0.f);
        if (m < MR)
            v = *(const float4*)(g_vbar + ((size_t)b * MR + m) * 64 + c4 * 4);
        int f = c4 * 4;
        sVT[(f + 0) * OPAD + cl] = v.x;
        sVT[(f + 1) * OPAD + cl] = v.y;
        sVT[(f + 2) * OPAD + cl] = v.z;
        sVT[(f + 3) * OPAD + cl] = v.w;
    }
    __syncthreads();

    int warp = tid >> 5;
    int lane = tid & 31;
    int o0 = warp * 8;           // whole warp shares this o-group
    int ml0 = lane * 4;          // lanes tile m

    ull acc2[2][8];   // p = m-pair (m, m+1), j = o
#pragma unroll
    for (int p = 0; p < 2; p++)
#pragma unroll
        for (int j = 0; j < 8; j++) acc2[p][j] = 0ull;

#pragma unroll 4
    for (int f = 0; f < 64; f++) {
        // uniform-address loads: one L1 transaction broadcast per warp
        float4 w0 = __ldg((const float4*)(g_WovT + f * 64 + o0));
        float4 w1 = __ldg((const float4*)(g_WovT + f * 64 + o0 + 4));
        float w[8] = {w0.x, w0.y, w0.z, w0.w, w1.x, w1.y, w1.z, w1.w};
        ull w2[8];
#pragma unroll
        for (int j = 0; j < 8; j++)
            asm("mov.b64 %0, {%1, %1};" : "=l"(w2[j]) : "f"(w[j]));
        const float* vrow = sVT + f * OPAD + ml0;   // f*134 even -> 8B aligned
        ull v2[2];
#pragma unroll
        for (int p = 0; p < 2; p++) v2[p] = *(const ull*)(vrow + 2 * p);
#pragma unroll
        for (int p = 0; p < 2; p++)
#pragma unroll
            for (int j = 0; j < 8; j++)
                asm("fma.rn.f32x2 %0, %1, %2, %0;"
                    : "+l"(acc2[p][j]) : "l"(v2[p]), "l"(w2[j]));
    }

    if (m0 + ml0 + 3 < MR) {      // MR % 4 == 0 -> all-or-nothing
#pragma unroll
        for (int j = 0; j < 8; j++) {
            int o = o0 + j;
            float a[4];
#pragma unroll
            for (int p = 0; p < 2; p++)
                asm("mov.b64 {%0, %1}, %2;" : "=f"(a[2 * p]), "=f"(a[2 * p + 1])
                    : "l"(acc2[p][j]));
            float* dst = out + ((size_t)b * CO + o) * MR + m0 + ml0;
            *(float4*)dst = make_float4(a[0], a[1], a[2], a[3]);
        }
    }
}

// ---------------- launch ----------------
extern "C" void kernel_launch(void* const* d_in, const int* in_sizes, int n_in,
                              void* d_out, int out_size) {
    const float* v_feat = (const float*)d_in[0];
    const float* r_feat = (const float*)d_in[1];
    const float* Wq = (const float*)d_in[2];
    const float* Wk = (const float*)d_in[3];
    const float* Wv = (const float*)d_in[4];
    const float* Wo = (const float*)d_in[5];
    const void* v2p = d_in[6];
    const void* r2p = d_in[7];
    float* out = (float*)d_out;

    cudaFuncSetAttribute(out3_kernel, cudaFuncAttributeMaxDynamicSharedMemorySize,
                         OUT3_BYTES);

    // 1) phase1: vT transpose || repack || zero || Wov fold || qd GEMM (one launch)
    phase1_kernel<<<P1_GRID, 256>>>(v_feat, r_feat, v2p, r2p, Wq, Wk, Wv, Wo);

    // 2) attention: batched gathers, softmax, RED into g_vbar
    attn_kernel<<<TOTN / 32, 256>>>();

    // 3) dense Wov GEMM, warp-broadcast W (__ldg) + direct store
    out3_kernel<<<dim3((MR + OTILE - 1) / OTILE, B_), 256, OUT3_BYTES>>>(out);
}

// round 15
// speedup vs baseline: 1.0005x; 1.0005x over previous
#include <cuda_runtime.h>
#include <cstddef>

// Problem constants (fixed by setup_inputs)
#define B_   2
#define CV   64
#define CR   20
#define E_   64
#define CO   64
#define MV   100000
#define MR   50000
#define NV   262144      // v2p count per batch
#define NN   65536       // bundles per batch (N / bundle, bundle = 4)
#define TOTN (B_ * NN)   // 131072
#define CELLS (B_ * MR)  // 100000

typedef unsigned long long ull;

// ---------------- scratch (device globals: allocation-free, 16B-aligned) ----------------
__device__ __align__(16) float g_vT[(size_t)B_ * MV * CV];    // v_feat^T: (B, Mv, 64)
__device__ __align__(16) float g_qd[(size_t)CELLS * 64];      // dense q per cell
__device__ __align__(16) float g_vbar[(size_t)CELLS * 64];    // per-cell summed vbar (RED)
__device__ __align__(16) float g_WkqT[CR * 64];               // [c][f]
__device__ __align__(16) float g_WovT[64 * 64];               // [f][o]
__device__ int   g_iv[(size_t)B_ * NV];                       // v indices (int32)
__device__ int   g_ir[(size_t)TOTN];                          // r indices (int32)

__device__ __forceinline__ bool detect_int64(const int* __restrict__ p) {
    bool i64 = true;
#pragma unroll
    for (int i = 1; i < 32; i += 2) i64 &= (p[i] == 0);
    return i64;
}

// ---------------- phase1: vT transpose + repack + zero + weight folds (lean) ----------------
#define TR_BX ((MV + 63) / 64)           // 1563
#define TR_BLKS (TR_BX * B_)             // 3126
#define RP_BLKS 256
#define ZR_BLKS 128
#define P1_GRID (TR_BLKS + RP_BLKS + ZR_BLKS + 3)

__global__ __launch_bounds__(256) void phase1_kernel(
    const float* __restrict__ v_feat,
    const void* __restrict__ v2p, const void* __restrict__ r2p,
    const float* __restrict__ Wq, const float* __restrict__ Wk,
    const float* __restrict__ Wv, const float* __restrict__ Wo) {
    __shared__ float sbuf[64 * 65 + 64 * 64];   // union: transpose tile / fold operands

    int blk = blockIdx.x;
    int tid = threadIdx.x;

    if (blk < TR_BLKS) {
        // ---- v transpose: (B, 64, Mv) -> (B, Mv, 64), float4 both sides ----
        float (*tile)[65] = (float (*)[65])sbuf;   // [m_local][c]
        int bx = blk % TR_BX;
        int b = blk / TR_BX;
        int m0 = bx * 64;
        const float* inb = v_feat + (size_t)b * CV * MV;
        float* outb = g_vT + (size_t)b * MV * CV;

#pragma unroll
        for (int j = 0; j < 4; j++) {
            int idx = tid + j * 256;
            int c = idx >> 4;
            int mq = idx & 15;
            int m = m0 + mq * 4;
            if (m < MV) {   // MV % 4 == 0
                float4 v = *(const float4*)(inb + (size_t)c * MV + m);
                tile[mq * 4 + 0][c] = v.x;
                tile[mq * 4 + 1][c] = v.y;
                tile[mq * 4 + 2][c] = v.z;
                tile[mq * 4 + 3][c] = v.w;
            }
        }
        __syncthreads();
#pragma unroll
        for (int j = 0; j < 4; j++) {
            int idx = tid + j * 256;
            int ml = idx >> 4;
            int cq = idx & 15;
            int m = m0 + ml;
            if (m < MV) {
                float4 v = make_float4(tile[ml][cq * 4 + 0], tile[ml][cq * 4 + 1],
                                       tile[ml][cq * 4 + 2], tile[ml][cq * 4 + 3]);
                *(float4*)(outb + (size_t)m * CV + cq * 4) = v;
            }
        }
    } else if (blk < TR_BLKS + RP_BLKS) {
        // ---- index repack (int32 or int64 source) ----
        const int* pv = (const int*)v2p;
        const int* pr = (const int*)r2p;
        bool v64 = detect_int64(pv);
        bool r64 = detect_int64(pr);
        int t = (blk - TR_BLKS) * 256 + tid;
        int stride = RP_BLKS * 256;
        for (int i = t; i < B_ * NV; i += stride)
            g_iv[i] = v64 ? pv[(size_t)4 * i] : pv[(size_t)2 * i];
        for (int i = t; i < TOTN; i += stride)
            g_ir[i] = r64 ? pr[(size_t)4 * i] : pr[(size_t)2 * i];
    } else if (blk < TR_BLKS + RP_BLKS + ZR_BLKS) {
        // ---- zero RED accumulator ----
        float4* p = (float4*)g_vbar;
        int n4 = (CELLS * 64) / 4;
        int t = (blk - TR_BLKS - RP_BLKS) * 256 + tid;
        int stride = ZR_BLKS * 256;
        float4 z = make_float4(0.f, 0.f, 0.f, 0.f);
        for (int i = t; i < n4; i += stride) p[i] = z;
    } else if (blk == TR_BLKS + RP_BLKS + ZR_BLKS) {
        // ---- Wkq fold ----
        float* sA = sbuf;             // Wk 64x64
        float* sB = sbuf + 64 * 65;   // Wq 64x20
        for (int i = tid; i < 64 * 64; i += 256) sA[i] = Wk[i];
        for (int i = tid; i < 64 * CR; i += 256) sB[i] = Wq[i];
        __syncthreads();
        for (int i = tid; i < CR * 64; i += 256) {
            int c = i >> 6, f = i & 63;
            float s = 0.f;
#pragma unroll
            for (int e = 0; e < 64; e++) s += sA[e * 64 + f] * sB[e * CR + c];
            g_WkqT[i] = s;  // [c][f]
        }
    } else {
        // ---- Wov fold (2 blocks) ----
        int half = blk - (TR_BLKS + RP_BLKS + ZR_BLKS + 1);  // 0 or 1
        float* sA = sbuf;             // Wv
        float* sB = sbuf + 64 * 65;   // Wo
        for (int i = tid; i < 64 * 64; i += 256) sA[i] = Wv[i];
        for (int i = tid; i < 64 * 64; i += 256) sB[i] = Wo[i];
        __syncthreads();
        for (int ii = half * 2048 + tid; ii < half * 2048 + 2048; ii += 256) {
            int f = ii >> 6, o = ii & 63;
            float s = 0.f;
#pragma unroll
            for (int e = 0; e < 64; e++) s += sB[o * 64 + e] * sA[e * 64 + f];
            g_WovT[ii] = s;  // [f][o]
        }
    }
}

// ---------------- dense q GEMM: g_qd[b][m][f] = sum_c r_feat[b][c][m] * Wkq[c][f] ----------------
#define QD_TILE 128
#define QD_PAD 132
__global__ __launch_bounds__(256) void qd_kernel(const float* __restrict__ r_feat) {
    __shared__ float sW[CR * 64];       // [c][f]
    __shared__ float sR[CR * QD_PAD];   // [c][m-local]

    int tid = threadIdx.x;
    int b = blockIdx.y;
    int m0 = blockIdx.x * QD_TILE;

    for (int i = tid; i < CR * 64; i += 256) sW[i] = g_WkqT[i];
    for (int i = tid; i < CR * QD_TILE; i += 256) {
        int c = i / QD_TILE;
        int m = i - c * QD_TILE;
        float v = 0.f;
        if (m0 + m < MR) v = r_feat[((size_t)b * CR + c) * MR + m0 + m];
        sR[c * QD_PAD + m] = v;
    }
    __syncthreads();

    int f0 = (tid & 7) * 8;
    int ml0 = (tid >> 3) * 4;

    ull acc2[4][4];   // p = f-pair, j = m
#pragma unroll
    for (int p = 0; p < 4; p++)
#pragma unroll
        for (int j = 0; j < 4; j++) acc2[p][j] = 0ull;

#pragma unroll
    for (int c = 0; c < CR; c++) {
        const float* wrow = sW + c * 64 + f0;
        ull w2[4];
#pragma unroll
        for (int p = 0; p < 4; p++) w2[p] = *(const ull*)(wrow + 2 * p);
        const float* vrow = sR + c * QD_PAD + ml0;
        ull v2[4];
#pragma unroll
        for (int j = 0; j < 4; j++) {
            float vj = vrow[j];
            asm("mov.b64 %0, {%1, %1};" : "=l"(v2[j]) : "f"(vj));
        }
#pragma unroll
        for (int p = 0; p < 4; p++)
#pragma unroll
            for (int j = 0; j < 4; j++)
                asm("fma.rn.f32x2 %0, %1, %2, %0;"
                    : "+l"(acc2[p][j]) : "l"(w2[p]), "l"(v2[j]));
    }

#pragma unroll
    for (int j = 0; j < 4; j++) {
        int m = m0 + ml0 + j;
        if (m < MR) {
            float a[8];
#pragma unroll
            for (int p = 0; p < 4; p++)
                asm("mov.b64 {%0, %1}, %2;" : "=f"(a[2 * p]), "=f"(a[2 * p + 1])
                    : "l"(acc2[p][j]));
            float* dst = g_qd + ((size_t)b * MR + m) * 64 + f0;
            *(float4*)dst = make_float4(a[0], a[1], a[2], a[3]);
            *(float4*)(dst + 4) = make_float4(a[4], a[5], a[6], a[7]);
        }
    }
}

// ---------------- attention: gather q + v (batched loads), softmax, RED into g_vbar ----------------
__global__ __launch_bounds__(256) void attn_kernel() {
    const unsigned FULL = 0xffffffffu;
    int gw = (blockIdx.x * 256 + threadIdx.x) >> 5;  // warp id, 4 bundles each
    int lane = threadIdx.x & 31;
    int sub = lane >> 3;
    int fl = lane & 7;

    int n = gw * 4 + sub;
    int b = n >> 16;

    int ldv = 0;
    if (lane < 16) ldv = g_iv[(size_t)gw * 16 + lane];
    else if (lane < 20) ldv = g_ir[gw * 4 + (lane - 16)];

    int ir_n = __shfl_sync(FULL, ldv, 16 + sub);
    int ivm[4];
#pragma unroll
    for (int m = 0; m < 4; m++) ivm[m] = __shfl_sync(FULL, ldv, sub * 4 + m);

    const float4* qp = (const float4*)(g_qd + ((size_t)b * MR + ir_n) * 64 + fl * 8);
    float4 q0 = qp[0];
    float4 q1 = qp[1];

    const float* vbase = g_vT + (size_t)b * MV * 64;
    float4 v0[4], v1[4];
#pragma unroll
    for (int m = 0; m < 4; m++) {
        const float4* vp = (const float4*)(vbase + (size_t)ivm[m] * 64 + fl * 8);
        v0[m] = vp[0];
        v1[m] = vp[1];
    }

    float s[4];
#pragma unroll
    for (int m = 0; m < 4; m++) {
        float p = q0.x * v0[m].x + q0.y * v0[m].y + q0.z * v0[m].z + q0.w * v0[m].w
                + q1.x * v1[m].x + q1.y * v1[m].y + q1.z * v1[m].z + q1.w * v1[m].w;
        p += __shfl_xor_sync(FULL, p, 4);
        p += __shfl_xor_sync(FULL, p, 2);
        p += __shfl_xor_sync(FULL, p, 1);
        s[m] = p * 0.125f;  // 1/sqrt(E=64)
    }

    float mx = fmaxf(fmaxf(s[0], s[1]), fmaxf(s[2], s[3]));
    float e0 = __expf(s[0] - mx), e1 = __expf(s[1] - mx);
    float e2 = __expf(s[2] - mx), e3 = __expf(s[3] - mx);
    float inv = 1.0f / (e0 + e1 + e2 + e3);
    e0 *= inv; e1 *= inv; e2 *= inv; e3 *= inv;

    float4 o0, o1;
    o0.x = e0 * v0[0].x + e1 * v0[1].x + e2 * v0[2].x + e3 * v0[3].x;
    o0.y = e0 * v0[0].y + e1 * v0[1].y + e2 * v0[2].y + e3 * v0[3].y;
    o0.z = e0 * v0[0].z + e1 * v0[1].z + e2 * v0[2].z + e3 * v0[3].z;
    o0.w = e0 * v0[0].w + e1 * v0[1].w + e2 * v0[2].w + e3 * v0[3].w;
    o1.x = e0 * v1[0].x + e1 * v1[1].x + e2 * v1[2].x + e3 * v1[3].x;
    o1.y = e0 * v1[0].y + e1 * v1[1].y + e2 * v1[2].y + e3 * v1[3].y;
    o1.z = e0 * v1[0].z + e1 * v1[1].z + e2 * v1[2].z + e3 * v1[3].z;
    o1.w = e0 * v1[0].w + e1 * v1[1].w + e2 * v1[2].w + e3 * v1[3].w;

    float* dst = g_vbar + ((size_t)b * MR + ir_n) * 64 + fl * 8;
    asm volatile("red.global.add.v4.f32 [%0], {%1, %2, %3, %4};"
                 :: "l"(dst), "f"(o0.x), "f"(o0.y), "f"(o0.z), "f"(o0.w) : "memory");
    asm volatile("red.global.add.v4.f32 [%0], {%1, %2, %3, %4};"
                 :: "l"(dst + 4), "f"(o1.x), "f"(o1.y), "f"(o1.z), "f"(o1.w) : "memory");
}

// ---------------- dense output GEMM: out[b][o][m] = sum_f Wov[f][o] * vbar[m][f] ----------------
// warp-broadcast W via uniform-address __ldg (L1-resident), sVT only in smem (~34 KB)
#define OTILE 128
#define OPAD 134
#define OUT3_FLOATS (64 * OPAD)
#define OUT3_BYTES  (OUT3_FLOATS * 4)

__global__ __launch_bounds__(256) void out3_kernel(float* __restrict__ out) {
    extern __shared__ float sVT[];   // [f][cl]

    int tid = threadIdx.x;
    int b = blockIdx.y;
    int m0 = blockIdx.x * OTILE;

    for (int i = tid; i < OTILE * 16; i += 256) {
        int cl = i >> 4;
        int c4 = i & 15;
        int m = m0 + cl;
        float4 v = make_float4(0.f, 0.f, 0.f, 0.f);
        if (m < MR)
            v = *(const float4*)(g_vbar + ((size_t)b * MR + m) * 64 + c4 * 4);
        int f = c4 * 4;
        sVT[(f + 0) * OPAD + cl] = v.x;
        sVT[(f + 1) * OPAD + cl] = v.y;
        sVT[(f + 2) * OPAD + cl] = v.z;
        sVT[(f + 3) * OPAD + cl] = v.w;
    }
    __syncthreads();

    int warp = tid >> 5;
    int lane = tid & 31;
    int o0 = warp * 8;           // whole warp shares this o-group
    int ml0 = lane * 4;          // lanes tile m

    ull acc2[2][8];   // p = m-pair (m, m+1), j = o
#pragma unroll
    for (int p = 0; p < 2; p++)
#pragma unroll
        for (int j = 0; j < 8; j++) acc2[p][j] = 0ull;

#pragma unroll 4
    for (int f = 0; f < 64; f++) {
        // uniform-address loads: one L1 transaction broadcast per warp
        float4 w0 = __ldg((const float4*)(g_WovT + f * 64 + o0));
        float4 w1 = __ldg((const float4*)(g_WovT + f * 64 + o0 + 4));
        float w[8] = {w0.x, w0.y, w0.z, w0.w, w1.x, w1.y, w1.z, w1.w};
        ull w2[8];
#pragma unroll
        for (int j = 0; j < 8; j++)
            asm("mov.b64 %0, {%1, %1};" : "=l"(w2[j]) : "f"(w[j]));
        const float* vrow = sVT + f * OPAD + ml0;   // f*134 even -> 8B aligned
        ull v2[2];
#pragma unroll
        for (int p = 0; p < 2; p++) v2[p] = *(const ull*)(vrow + 2 * p);
#pragma unroll
        for (int p = 0; p < 2; p++)
#pragma unroll
            for (int j = 0; j < 8; j++)
                asm("fma.rn.f32x2 %0, %1, %2, %0;"
                    : "+l"(acc2[p][j]) : "l"(v2[p]), "l"(w2[j]));
    }

    if (m0 + ml0 + 3 < MR) {      // MR % 4 == 0 -> all-or-nothing
#pragma unroll
        for (int j = 0; j < 8; j++) {
            int o = o0 + j;
            float a[4];
#pragma unroll
            for (int p = 0; p < 2; p++)
                asm("mov.b64 {%0, %1}, %2;" : "=f"(a[2 * p]), "=f"(a[2 * p + 1])
                    : "l"(acc2[p][j]));
            float* dst = out + ((size_t)b * CO + o) * MR + m0 + ml0;
            *(float4*)dst = make_float4(a[0], a[1], a[2], a[3]);
        }
    }
}

// ---------------- launch ----------------
extern "C" void kernel_launch(void* const* d_in, const int* in_sizes, int n_in,
                              void* d_out, int out_size) {
    const float* v_feat = (const float*)d_in[0];
    const float* r_feat = (const float*)d_in[1];
    const float* Wq = (const float*)d_in[2];
    const float* Wk = (const float*)d_in[3];
    const float* Wv = (const float*)d_in[4];
    const float* Wo = (const float*)d_in[5];
    const void* v2p = d_in[6];
    const void* r2p = d_in[7];
    float* out = (float*)d_out;

    cudaFuncSetAttribute(out3_kernel, cudaFuncAttributeMaxDynamicSharedMemorySize,
                         OUT3_BYTES);

    // 1) phase1 (lean): vT transpose || repack || zero || weight folds
    phase1_kernel<<<P1_GRID, 256>>>(v_feat, v2p, r2p, Wq, Wk, Wv, Wo);

    // 2) dense q GEMM (standalone: keeps phase1 resource-light)
    qd_kernel<<<dim3((MR + QD_TILE - 1) / QD_TILE, B_), 256>>>(r_feat);

    // 3) attention: batched gathers, softmax, RED into g_vbar
    attn_kernel<<<TOTN / 32, 256>>>();

    // 4) dense Wov GEMM, warp-broadcast W (__ldg) + direct store
    out3_kernel<<<dim3((MR + OTILE - 1) / OTILE, B_), 256, OUT3_BYTES>>>(out);
}

// round 16
// speedup vs baseline: 1.0997x; 1.0991x over previous
#include <cuda_runtime.h>
#include <cstddef>

// Problem constants (fixed by setup_inputs)
#define B_   2
#define CV   64
#define CR   20
#define E_   64
#define CO   64
#define MV   100000
#define MR   50000
#define NV   262144      // v2p count per batch
#define NN   65536       // bundles per batch (N / bundle, bundle = 4)
#define TOTN (B_ * NN)   // 131072
#define CELLS (B_ * MR)  // 100000

typedef unsigned long long ull;

// ---------------- scratch (device globals: allocation-free, 16B-aligned) ----------------
__device__ __align__(16) float g_vT[(size_t)B_ * MV * CV];    // v_feat^T: (B, Mv, 64)
__device__ __align__(16) float g_qd[(size_t)CELLS * 64];      // dense q per cell
__device__ __align__(16) float g_vbar[(size_t)CELLS * 64];    // per-cell summed vbar (RED)
__device__ __align__(16) float g_WkqT[CR * 64];               // [c][f]
__device__ __align__(16) float g_WovT[64 * 64];               // [f][o]
__device__ int   g_iv[(size_t)B_ * NV];                       // v indices (int32)
__device__ int   g_ir[(size_t)TOTN];                          // r indices (int32)

__device__ __forceinline__ bool detect_int64(const int* __restrict__ p) {
    bool i64 = true;
#pragma unroll
    for (int i = 1; i < 32; i += 2) i64 &= (p[i] == 0);
    return i64;
}

// ---------------- phase1: vT transpose + repack + zero + weight folds (lean) ----------------
#define TR_BX ((MV + 63) / 64)           // 1563
#define TR_BLKS (TR_BX * B_)             // 3126
#define RP_BLKS 256
#define ZR_BLKS 128
#define P1_GRID (TR_BLKS + RP_BLKS + ZR_BLKS + 3)

__global__ __launch_bounds__(256) void phase1_kernel(
    const float* __restrict__ v_feat,
    const void* __restrict__ v2p, const void* __restrict__ r2p,
    const float* __restrict__ Wq, const float* __restrict__ Wk,
    const float* __restrict__ Wv, const float* __restrict__ Wo) {
    __shared__ float sbuf[64 * 65 + 64 * 64];   // union: transpose tile / fold operands

    int blk = blockIdx.x;
    int tid = threadIdx.x;

    if (blk < TR_BLKS) {
        // ---- v transpose: (B, 64, Mv) -> (B, Mv, 64), float4 both sides ----
        float (*tile)[65] = (float (*)[65])sbuf;   // [m_local][c]
        int bx = blk % TR_BX;
        int b = blk / TR_BX;
        int m0 = bx * 64;
        const float* inb = v_feat + (size_t)b * CV * MV;
        float* outb = g_vT + (size_t)b * MV * CV;

#pragma unroll
        for (int j = 0; j < 4; j++) {
            int idx = tid + j * 256;
            int c = idx >> 4;
            int mq = idx & 15;
            int m = m0 + mq * 4;
            if (m < MV) {   // MV % 4 == 0
                float4 v = *(const float4*)(inb + (size_t)c * MV + m);
                tile[mq * 4 + 0][c] = v.x;
                tile[mq * 4 + 1][c] = v.y;
                tile[mq * 4 + 2][c] = v.z;
                tile[mq * 4 + 3][c] = v.w;
            }
        }
        __syncthreads();
#pragma unroll
        for (int j = 0; j < 4; j++) {
            int idx = tid + j * 256;
            int ml = idx >> 4;
            int cq = idx & 15;
            int m = m0 + ml;
            if (m < MV) {
                float4 v = make_float4(tile[ml][cq * 4 + 0], tile[ml][cq * 4 + 1],
                                       tile[ml][cq * 4 + 2], tile[ml][cq * 4 + 3]);
                *(float4*)(outb + (size_t)m * CV + cq * 4) = v;
            }
        }
    } else if (blk < TR_BLKS + RP_BLKS) {
        // ---- index repack (int32 or int64 source) ----
        const int* pv = (const int*)v2p;
        const int* pr = (const int*)r2p;
        bool v64 = detect_int64(pv);
        bool r64 = detect_int64(pr);
        int t = (blk - TR_BLKS) * 256 + tid;
        int stride = RP_BLKS * 256;
        for (int i = t; i < B_ * NV; i += stride)
            g_iv[i] = v64 ? pv[(size_t)4 * i] : pv[(size_t)2 * i];
        for (int i = t; i < TOTN; i += stride)
            g_ir[i] = r64 ? pr[(size_t)4 * i] : pr[(size_t)2 * i];
    } else if (blk < TR_BLKS + RP_BLKS + ZR_BLKS) {
        // ---- zero RED accumulator ----
        float4* p = (float4*)g_vbar;
        int n4 = (CELLS * 64) / 4;
        int t = (blk - TR_BLKS - RP_BLKS) * 256 + tid;
        int stride = ZR_BLKS * 256;
        float4 z = make_float4(0.f, 0.f, 0.f, 0.f);
        for (int i = t; i < n4; i += stride) p[i] = z;
    } else if (blk == TR_BLKS + RP_BLKS + ZR_BLKS) {
        // ---- Wkq fold ----
        float* sA = sbuf;             // Wk 64x64
        float* sB = sbuf + 64 * 65;   // Wq 64x20
        for (int i = tid; i < 64 * 64; i += 256) sA[i] = Wk[i];
        for (int i = tid; i < 64 * CR; i += 256) sB[i] = Wq[i];
        __syncthreads();
        for (int i = tid; i < CR * 64; i += 256) {
            int c = i >> 6, f = i & 63;
            float s = 0.f;
#pragma unroll
            for (int e = 0; e < 64; e++) s += sA[e * 64 + f] * sB[e * CR + c];
            g_WkqT[i] = s;  // [c][f]
        }
    } else {
        // ---- Wov fold (2 blocks) ----
        int half = blk - (TR_BLKS + RP_BLKS + ZR_BLKS + 1);  // 0 or 1
        float* sA = sbuf;             // Wv
        float* sB = sbuf + 64 * 65;   // Wo
        for (int i = tid; i < 64 * 64; i += 256) sA[i] = Wv[i];
        for (int i = tid; i < 64 * 64; i += 256) sB[i] = Wo[i];
        __syncthreads();
        for (int ii = half * 2048 + tid; ii < half * 2048 + 2048; ii += 256) {
            int f = ii >> 6, o = ii & 63;
            float s = 0.f;
#pragma unroll
            for (int e = 0; e < 64; e++) s += sB[o * 64 + e] * sA[e * 64 + f];
            g_WovT[ii] = s;  // [f][o]
        }
    }
}

// ---------------- dense q GEMM: g_qd[b][m][f] = sum_c r_feat[b][c][m] * Wkq[c][f] ----------------
#define QD_TILE 128
#define QD_PAD 132
__global__ __launch_bounds__(256) void qd_kernel(const float* __restrict__ r_feat) {
    __shared__ float sW[CR * 64];       // [c][f]
    __shared__ float sR[CR * QD_PAD];   // [c][m-local]

    int tid = threadIdx.x;
    int b = blockIdx.y;
    int m0 = blockIdx.x * QD_TILE;

    for (int i = tid; i < CR * 64; i += 256) sW[i] = g_WkqT[i];
    for (int i = tid; i < CR * QD_TILE; i += 256) {
        int c = i / QD_TILE;
        int m = i - c * QD_TILE;
        float v = 0.f;
        if (m0 + m < MR) v = r_feat[((size_t)b * CR + c) * MR + m0 + m];
        sR[c * QD_PAD + m] = v;
    }
    __syncthreads();

    int f0 = (tid & 7) * 8;
    int ml0 = (tid >> 3) * 4;

    ull acc2[4][4];   // p = f-pair, j = m
#pragma unroll
    for (int p = 0; p < 4; p++)
#pragma unroll
        for (int j = 0; j < 4; j++) acc2[p][j] = 0ull;

#pragma unroll
    for (int c = 0; c < CR; c++) {
        const float* wrow = sW + c * 64 + f0;
        ull w2[4];
#pragma unroll
        for (int p = 0; p < 4; p++) w2[p] = *(const ull*)(wrow + 2 * p);
        const float* vrow = sR + c * QD_PAD + ml0;
        ull v2[4];
#pragma unroll
        for (int j = 0; j < 4; j++) {
            float vj = vrow[j];
            asm("mov.b64 %0, {%1, %1};" : "=l"(v2[j]) : "f"(vj));
        }
#pragma unroll
        for (int p = 0; p < 4; p++)
#pragma unroll
            for (int j = 0; j < 4; j++)
                asm("fma.rn.f32x2 %0, %1, %2, %0;"
                    : "+l"(acc2[p][j]) : "l"(w2[p]), "l"(v2[j]));
    }

#pragma unroll
    for (int j = 0; j < 4; j++) {
        int m = m0 + ml0 + j;
        if (m < MR) {
            float a[8];
#pragma unroll
            for (int p = 0; p < 4; p++)
                asm("mov.b64 {%0, %1}, %2;" : "=f"(a[2 * p]), "=f"(a[2 * p + 1])
                    : "l"(acc2[p][j]));
            float* dst = g_qd + ((size_t)b * MR + m) * 64 + f0;
            *(float4*)dst = make_float4(a[0], a[1], a[2], a[3]);
            *(float4*)(dst + 4) = make_float4(a[4], a[5], a[6], a[7]);
        }
    }
}

// ---------------- attention: gather q + v (batched loads), softmax, RED into g_vbar ----------------
__global__ __launch_bounds__(256) void attn_kernel() {
    const unsigned FULL = 0xffffffffu;
    int gw = (blockIdx.x * 256 + threadIdx.x) >> 5;  // warp id, 4 bundles each
    int lane = threadIdx.x & 31;
    int sub = lane >> 3;
    int fl = lane & 7;

    int n = gw * 4 + sub;
    int b = n >> 16;

    int ldv = 0;
    if (lane < 16) ldv = g_iv[(size_t)gw * 16 + lane];
    else if (lane < 20) ldv = g_ir[gw * 4 + (lane - 16)];

    int ir_n = __shfl_sync(FULL, ldv, 16 + sub);
    int ivm[4];
#pragma unroll
    for (int m = 0; m < 4; m++) ivm[m] = __shfl_sync(FULL, ldv, sub * 4 + m);

    const float4* qp = (const float4*)(g_qd + ((size_t)b * MR + ir_n) * 64 + fl * 8);
    float4 q0 = qp[0];
    float4 q1 = qp[1];

    const float* vbase = g_vT + (size_t)b * MV * 64;
    float4 v0[4], v1[4];
#pragma unroll
    for (int m = 0; m < 4; m++) {
        const float4* vp = (const float4*)(vbase + (size_t)ivm[m] * 64 + fl * 8);
        v0[m] = vp[0];
        v1[m] = vp[1];
    }

    float s[4];
#pragma unroll
    for (int m = 0; m < 4; m++) {
        float p = q0.x * v0[m].x + q0.y * v0[m].y + q0.z * v0[m].z + q0.w * v0[m].w
                + q1.x * v1[m].x + q1.y * v1[m].y + q1.z * v1[m].z + q1.w * v1[m].w;
        p += __shfl_xor_sync(FULL, p, 4);
        p += __shfl_xor_sync(FULL, p, 2);
        p += __shfl_xor_sync(FULL, p, 1);
        s[m] = p * 0.125f;  // 1/sqrt(E=64)
    }

    float mx = fmaxf(fmaxf(s[0], s[1]), fmaxf(s[2], s[3]));
    float e0 = __expf(s[0] - mx), e1 = __expf(s[1] - mx);
    float e2 = __expf(s[2] - mx), e3 = __expf(s[3] - mx);
    float inv = 1.0f / (e0 + e1 + e2 + e3);
    e0 *= inv; e1 *= inv; e2 *= inv; e3 *= inv;

    float4 o0, o1;
    o0.x = e0 * v0[0].x + e1 * v0[1].x + e2 * v0[2].x + e3 * v0[3].x;
    o0.y = e0 * v0[0].y + e1 * v0[1].y + e2 * v0[2].y + e3 * v0[3].y;
    o0.z = e0 * v0[0].z + e1 * v0[1].z + e2 * v0[2].z + e3 * v0[3].z;
    o0.w = e0 * v0[0].w + e1 * v0[1].w + e2 * v0[2].w + e3 * v0[3].w;
    o1.x = e0 * v1[0].x + e1 * v1[1].x + e2 * v1[2].x + e3 * v1[3].x;
    o1.y = e0 * v1[0].y + e1 * v1[1].y + e2 * v1[2].y + e3 * v1[3].y;
    o1.z = e0 * v1[0].z + e1 * v1[1].z + e2 * v1[2].z + e3 * v1[3].z;
    o1.w = e0 * v1[0].w + e1 * v1[1].w + e2 * v1[2].w + e3 * v1[3].w;

    float* dst = g_vbar + ((size_t)b * MR + ir_n) * 64 + fl * 8;
    asm volatile("red.global.add.v4.f32 [%0], {%1, %2, %3, %4};"
                 :: "l"(dst), "f"(o0.x), "f"(o0.y), "f"(o0.z), "f"(o0.w) : "memory");
    asm volatile("red.global.add.v4.f32 [%0], {%1, %2, %3, %4};"
                 :: "l"(dst + 4), "f"(o1.x), "f"(o1.y), "f"(o1.z), "f"(o1.w) : "memory");
}

// ---------------- dense output GEMM: out[b][o][m] = sum_f Wov[f][o] * vbar[m][f] ----------------
// R12-measured config (sW smem + warp-broadcast + OPAD 132) with 2-way staging remap:
// thread stages half a vbar row (cl = tid>>1, half = tid&1) -> per-store banks = cl mod 32.
#define OTILE 128
#define OPAD 132
#define OUT3_FLOATS (64 * 64 + 64 * OPAD)
#define OUT3_BYTES  (OUT3_FLOATS * 4)

__global__ __launch_bounds__(256) void out3_kernel(float* __restrict__ out) {
    extern __shared__ float dsm[];
    float* sW = dsm;                 // [f][o]
    float* sVT = dsm + 64 * 64;      // [f][cl]

    int tid = threadIdx.x;
    int b = blockIdx.y;
    int m0 = blockIdx.x * OTILE;

    {
        float4* d4 = (float4*)sW;
        const float4* s4 = (const float4*)g_WovT;
        for (int i = tid; i < 1024; i += 256) d4[i] = s4[i];
    }
    // staging: 2 threads per row; lanes in a warp hit 16 distinct banks (2-way max)
    {
        int cl = tid >> 1;
        int half = tid & 1;
        int m = m0 + cl;
        const float4* src = (const float4*)(g_vbar + ((size_t)b * MR + m) * 64 + half * 32);
        bool ok = (m < MR);
#pragma unroll
        for (int k = 0; k < 8; k++) {
            float4 v = ok ? src[k] : make_float4(0.f, 0.f, 0.f, 0.f);
            int f = half * 32 + k * 4;
            sVT[(f + 0) * OPAD + cl] = v.x;
            sVT[(f + 1) * OPAD + cl] = v.y;
            sVT[(f + 2) * OPAD + cl] = v.z;
            sVT[(f + 3) * OPAD + cl] = v.w;
        }
    }
    __syncthreads();

    int warp = tid >> 5;
    int lane = tid & 31;
    int o0 = warp * 8;           // whole warp shares this o-group -> broadcast W reads
    int ml0 = lane * 4;          // lanes tile m

    ull acc2[2][8];   // p = m-pair (m, m+1), j = o
#pragma unroll
    for (int p = 0; p < 2; p++)
#pragma unroll
        for (int j = 0; j < 8; j++) acc2[p][j] = 0ull;

#pragma unroll 4
    for (int f = 0; f < 64; f++) {
        const float* wrow = sW + f * 64 + o0;   // same address across warp: broadcast
        float4 w0 = *(const float4*)wrow;
        float4 w1 = *(const float4*)(wrow + 4);
        float w[8] = {w0.x, w0.y, w0.z, w0.w, w1.x, w1.y, w1.z, w1.w};
        ull w2[8];
#pragma unroll
        for (int j = 0; j < 8; j++)
            asm("mov.b64 %0, {%1, %1};" : "=l"(w2[j]) : "f"(w[j]));
        const float* vrow = sVT + f * OPAD + ml0;   // OPAD even -> 8B aligned
        ull v2[2];
#pragma unroll
        for (int p = 0; p < 2; p++) v2[p] = *(const ull*)(vrow + 2 * p);
#pragma unroll
        for (int p = 0; p < 2; p++)
#pragma unroll
            for (int j = 0; j < 8; j++)
                asm("fma.rn.f32x2 %0, %1, %2, %0;"
                    : "+l"(acc2[p][j]) : "l"(v2[p]), "l"(w2[j]));
    }

    if (m0 + ml0 + 3 < MR) {      // MR % 4 == 0 -> all-or-nothing
#pragma unroll
        for (int j = 0; j < 8; j++) {
            int o = o0 + j;
            float a[4];
#pragma unroll
            for (int p = 0; p < 2; p++)
                asm("mov.b64 {%0, %1}, %2;" : "=f"(a[2 * p]), "=f"(a[2 * p + 1])
                    : "l"(acc2[p][j]));
            float* dst = out + ((size_t)b * CO + o) * MR + m0 + ml0;
            *(float4*)dst = make_float4(a[0], a[1], a[2], a[3]);
        }
    }
}

// ---------------- launch ----------------
extern "C" void kernel_launch(void* const* d_in, const int* in_sizes, int n_in,
                              void* d_out, int out_size) {
    const float* v_feat = (const float*)d_in[0];
    const float* r_feat = (const float*)d_in[1];
    const float* Wq = (const float*)d_in[2];
    const float* Wk = (const float*)d_in[3];
    const float* Wv = (const float*)d_in[4];
    const float* Wo = (const float*)d_in[5];
    const void* v2p = d_in[6];
    const void* r2p = d_in[7];
    float* out = (float*)d_out;

    cudaFuncSetAttribute(out3_kernel, cudaFuncAttributeMaxDynamicSharedMemorySize,
                         OUT3_BYTES);

    // 1) phase1 (lean): vT transpose || repack || zero || weight folds
    phase1_kernel<<<P1_GRID, 256>>>(v_feat, v2p, r2p, Wq, Wk, Wv, Wo);

    // 2) dense q GEMM
    qd_kernel<<<dim3((MR + QD_TILE - 1) / QD_TILE, B_), 256>>>(r_feat);

    // 3) attention: batched gathers, softmax, RED into g_vbar
    attn_kernel<<<TOTN / 32, 256>>>();

    // 4) dense Wov GEMM (R12 config + 2-way staging) + direct store
    out3_kernel<<<dim3((MR + OTILE - 1) / OTILE, B_), 256, OUT3_BYTES>>>(out);
}

// round 17
// speedup vs baseline: 1.1104x; 1.0097x over previous
#include <cuda_runtime.h>
#include <cstddef>

// Problem constants (fixed by setup_inputs)
#define B_   2
#define CV   64
#define CR   20
#define E_   64
#define CO   64
#define MV   100000
#define MR   50000
#define NV   262144      // v2p count per batch
#define NN   65536       // bundles per batch (N / bundle, bundle = 4)
#define TOTN (B_ * NN)   // 131072
#define CELLS (B_ * MR)  // 100000

typedef unsigned long long ull;

// ---------------- scratch (device globals: allocation-free, 16B-aligned) ----------------
__device__ __align__(16) float g_vT[(size_t)B_ * MV * CV];    // v_feat^T: (B, Mv, 64)
__device__ __align__(16) float g_qd[(size_t)CELLS * 64];      // dense q per cell
__device__ __align__(16) float g_vbar[(size_t)CELLS * 64];    // per-cell summed vbar (RED)
__device__ __align__(16) float g_WkqT[CR * 64];               // [c][f]
__device__ __align__(16) float g_WovT[64 * 64];               // [f][o]
__device__ int   g_iv[(size_t)B_ * NV];                       // v indices (int32)
__device__ int   g_ir[(size_t)TOTN];                          // r indices (int32)

__device__ __forceinline__ bool detect_int64(const int* __restrict__ p) {
    bool i64 = true;
#pragma unroll
    for (int i = 1; i < 32; i += 2) i64 &= (p[i] == 0);
    return i64;
}

// ---------------- phase1: vT transpose + repack + zero + weight folds (lean) ----------------
#define TR_BX ((MV + 63) / 64)           // 1563
#define TR_BLKS (TR_BX * B_)             // 3126
#define RP_BLKS 256
#define ZR_BLKS 128
#define P1_GRID (TR_BLKS + RP_BLKS + ZR_BLKS + 3)

__global__ __launch_bounds__(256) void phase1_kernel(
    const float* __restrict__ v_feat,
    const void* __restrict__ v2p, const void* __restrict__ r2p,
    const float* __restrict__ Wq, const float* __restrict__ Wk,
    const float* __restrict__ Wv, const float* __restrict__ Wo) {
    __shared__ float sbuf[64 * 65 + 64 * 64];   // union: transpose tile / fold operands

    int blk = blockIdx.x;
    int tid = threadIdx.x;

    if (blk < TR_BLKS) {
        // ---- v transpose: (B, 64, Mv) -> (B, Mv, 64), float4 both sides ----
        float (*tile)[65] = (float (*)[65])sbuf;   // [m_local][c]
        int bx = blk % TR_BX;
        int b = blk / TR_BX;
        int m0 = bx * 64;
        const float* inb = v_feat + (size_t)b * CV * MV;
        float* outb = g_vT + (size_t)b * MV * CV;

#pragma unroll
        for (int j = 0; j < 4; j++) {
            int idx = tid + j * 256;
            int c = idx >> 4;
            int mq = idx & 15;
            int m = m0 + mq * 4;
            if (m < MV) {   // MV % 4 == 0
                float4 v = *(const float4*)(inb + (size_t)c * MV + m);
                tile[mq * 4 + 0][c] = v.x;
                tile[mq * 4 + 1][c] = v.y;
                tile[mq * 4 + 2][c] = v.z;
                tile[mq * 4 + 3][c] = v.w;
            }
        }
        __syncthreads();
#pragma unroll
        for (int j = 0; j < 4; j++) {
            int idx = tid + j * 256;
            int ml = idx >> 4;
            int cq = idx & 15;
            int m = m0 + ml;
            if (m < MV) {
                float4 v = make_float4(tile[ml][cq * 4 + 0], tile[ml][cq * 4 + 1],
                                       tile[ml][cq * 4 + 2], tile[ml][cq * 4 + 3]);
                *(float4*)(outb + (size_t)m * CV + cq * 4) = v;
            }
        }
    } else if (blk < TR_BLKS + RP_BLKS) {
        // ---- index repack (int32 or int64 source) ----
        const int* pv = (const int*)v2p;
        const int* pr = (const int*)r2p;
        bool v64 = detect_int64(pv);
        bool r64 = detect_int64(pr);
        int t = (blk - TR_BLKS) * 256 + tid;
        int stride = RP_BLKS * 256;
        for (int i = t; i < B_ * NV; i += stride)
            g_iv[i] = v64 ? pv[(size_t)4 * i] : pv[(size_t)2 * i];
        for (int i = t; i < TOTN; i += stride)
            g_ir[i] = r64 ? pr[(size_t)4 * i] : pr[(size_t)2 * i];
    } else if (blk < TR_BLKS + RP_BLKS + ZR_BLKS) {
        // ---- zero RED accumulator ----
        float4* p = (float4*)g_vbar;
        int n4 = (CELLS * 64) / 4;
        int t = (blk - TR_BLKS - RP_BLKS) * 256 + tid;
        int stride = ZR_BLKS * 256;
        float4 z = make_float4(0.f, 0.f, 0.f, 0.f);
        for (int i = t; i < n4; i += stride) p[i] = z;
    } else if (blk == TR_BLKS + RP_BLKS + ZR_BLKS) {
        // ---- Wkq fold ----
        float* sA = sbuf;             // Wk 64x64
        float* sB = sbuf + 64 * 65;   // Wq 64x20
        for (int i = tid; i < 64 * 64; i += 256) sA[i] = Wk[i];
        for (int i = tid; i < 64 * CR; i += 256) sB[i] = Wq[i];
        __syncthreads();
        for (int i = tid; i < CR * 64; i += 256) {
            int c = i >> 6, f = i & 63;
            float s = 0.f;
#pragma unroll
            for (int e = 0; e < 64; e++) s += sA[e * 64 + f] * sB[e * CR + c];
            g_WkqT[i] = s;  // [c][f]
        }
    } else {
        // ---- Wov fold (2 blocks) ----
        int half = blk - (TR_BLKS + RP_BLKS + ZR_BLKS + 1);  // 0 or 1
        float* sA = sbuf;             // Wv
        float* sB = sbuf + 64 * 65;   // Wo
        for (int i = tid; i < 64 * 64; i += 256) sA[i] = Wv[i];
        for (int i = tid; i < 64 * 64; i += 256) sB[i] = Wo[i];
        __syncthreads();
        for (int ii = half * 2048 + tid; ii < half * 2048 + 2048; ii += 256) {
            int f = ii >> 6, o = ii & 63;
            float s = 0.f;
#pragma unroll
            for (int e = 0; e < 64; e++) s += sB[o * 64 + e] * sA[e * 64 + f];
            g_WovT[ii] = s;  // [f][o]
        }
    }
}

// ---------------- dense q GEMM: g_qd[b][m][f] = sum_c r_feat[b][c][m] * Wkq[c][f] ----------------
#define QD_TILE 128
#define QD_PAD 132
__global__ __launch_bounds__(256) void qd_kernel(const float* __restrict__ r_feat) {
    __shared__ float sW[CR * 64];       // [c][f]
    __shared__ float sR[CR * QD_PAD];   // [c][m-local]

    int tid = threadIdx.x;
    int b = blockIdx.y;
    int m0 = blockIdx.x * QD_TILE;

    for (int i = tid; i < CR * 64; i += 256) sW[i] = g_WkqT[i];
    for (int i = tid; i < CR * QD_TILE; i += 256) {
        int c = i / QD_TILE;
        int m = i - c * QD_TILE;
        float v = 0.f;
        if (m0 + m < MR) v = r_feat[((size_t)b * CR + c) * MR + m0 + m];
        sR[c * QD_PAD + m] = v;
    }
    __syncthreads();

    int f0 = (tid & 7) * 8;
    int ml0 = (tid >> 3) * 4;

    ull acc2[4][4];   // p = f-pair, j = m
#pragma unroll
    for (int p = 0; p < 4; p++)
#pragma unroll
        for (int j = 0; j < 4; j++) acc2[p][j] = 0ull;

#pragma unroll
    for (int c = 0; c < CR; c++) {
        const float* wrow = sW + c * 64 + f0;
        ull w2[4];
#pragma unroll
        for (int p = 0; p < 4; p++) w2[p] = *(const ull*)(wrow + 2 * p);
        const float* vrow = sR + c * QD_PAD + ml0;
        ull v2[4];
#pragma unroll
        for (int j = 0; j < 4; j++) {
            float vj = vrow[j];
            asm("mov.b64 %0, {%1, %1};" : "=l"(v2[j]) : "f"(vj));
        }
#pragma unroll
        for (int p = 0; p < 4; p++)
#pragma unroll
            for (int j = 0; j < 4; j++)
                asm("fma.rn.f32x2 %0, %1, %2, %0;"
                    : "+l"(acc2[p][j]) : "l"(w2[p]), "l"(v2[j]));
    }

#pragma unroll
    for (int j = 0; j < 4; j++) {
        int m = m0 + ml0 + j;
        if (m < MR) {
            float a[8];
#pragma unroll
            for (int p = 0; p < 4; p++)
                asm("mov.b64 {%0, %1}, %2;" : "=f"(a[2 * p]), "=f"(a[2 * p + 1])
                    : "l"(acc2[p][j]));
            float* dst = g_qd + ((size_t)b * MR + m) * 64 + f0;
            *(float4*)dst = make_float4(a[0], a[1], a[2], a[3]);
            *(float4*)(dst + 4) = make_float4(a[4], a[5], a[6], a[7]);
        }
    }
}

// ---------------- attention: gather q + v (batched loads), softmax, RED into g_vbar ----------------
__global__ __launch_bounds__(256) void attn_kernel() {
    const unsigned FULL = 0xffffffffu;
    int gw = (blockIdx.x * 256 + threadIdx.x) >> 5;  // warp id, 4 bundles each
    int lane = threadIdx.x & 31;
    int sub = lane >> 3;
    int fl = lane & 7;

    int n = gw * 4 + sub;
    int b = n >> 16;

    int ldv = 0;
    if (lane < 16) ldv = g_iv[(size_t)gw * 16 + lane];
    else if (lane < 20) ldv = g_ir[gw * 4 + (lane - 16)];

    int ir_n = __shfl_sync(FULL, ldv, 16 + sub);
    int ivm[4];
#pragma unroll
    for (int m = 0; m < 4; m++) ivm[m] = __shfl_sync(FULL, ldv, sub * 4 + m);

    const float4* qp = (const float4*)(g_qd + ((size_t)b * MR + ir_n) * 64 + fl * 8);
    float4 q0 = qp[0];
    float4 q1 = qp[1];

    const float* vbase = g_vT + (size_t)b * MV * 64;
    float4 v0[4], v1[4];
#pragma unroll
    for (int m = 0; m < 4; m++) {
        const float4* vp = (const float4*)(vbase + (size_t)ivm[m] * 64 + fl * 8);
        v0[m] = vp[0];
        v1[m] = vp[1];
    }

    float s[4];
#pragma unroll
    for (int m = 0; m < 4; m++) {
        float p = q0.x * v0[m].x + q0.y * v0[m].y + q0.z * v0[m].z + q0.w * v0[m].w
                + q1.x * v1[m].x + q1.y * v1[m].y + q1.z * v1[m].z + q1.w * v1[m].w;
        p += __shfl_xor_sync(FULL, p, 4);
        p += __shfl_xor_sync(FULL, p, 2);
        p += __shfl_xor_sync(FULL, p, 1);
        s[m] = p * 0.125f;  // 1/sqrt(E=64)
    }

    float mx = fmaxf(fmaxf(s[0], s[1]), fmaxf(s[2], s[3]));
    float e0 = __expf(s[0] - mx), e1 = __expf(s[1] - mx);
    float e2 = __expf(s[2] - mx), e3 = __expf(s[3] - mx);
    float inv = 1.0f / (e0 + e1 + e2 + e3);
    e0 *= inv; e1 *= inv; e2 *= inv; e3 *= inv;

    float4 o0, o1;
    o0.x = e0 * v0[0].x + e1 * v0[1].x + e2 * v0[2].x + e3 * v0[3].x;
    o0.y = e0 * v0[0].y + e1 * v0[1].y + e2 * v0[2].y + e3 * v0[3].y;
    o0.z = e0 * v0[0].z + e1 * v0[1].z + e2 * v0[2].z + e3 * v0[3].z;
    o0.w = e0 * v0[0].w + e1 * v0[1].w + e2 * v0[2].w + e3 * v0[3].w;
    o1.x = e0 * v1[0].x + e1 * v1[1].x + e2 * v1[2].x + e3 * v1[3].x;
    o1.y = e0 * v1[0].y + e1 * v1[1].y + e2 * v1[2].y + e3 * v1[3].y;
    o1.z = e0 * v1[0].z + e1 * v1[1].z + e2 * v1[2].z + e3 * v1[3].z;
    o1.w = e0 * v1[0].w + e1 * v1[1].w + e2 * v1[2].w + e3 * v1[3].w;

    float* dst = g_vbar + ((size_t)b * MR + ir_n) * 64 + fl * 8;
    asm volatile("red.global.add.v4.f32 [%0], {%1, %2, %3, %4};"
                 :: "l"(dst), "f"(o0.x), "f"(o0.y), "f"(o0.z), "f"(o0.w) : "memory");
    asm volatile("red.global.add.v4.f32 [%0], {%1, %2, %3, %4};"
                 :: "l"(dst + 4), "f"(o1.x), "f"(o1.y), "f"(o1.z), "f"(o1.w) : "memory");
}

// ---------------- dense output GEMM: out[b][o][m] = sum_f Wov[f][o] * vbar[m][f] ----------------
// o-paired f32x2: W pairs load naturally (broadcast LDS.64, no packing MOVs);
// only v (4 values/f) needs dup-packing. ~20% fewer instructions in the hot loop.
#define OTILE 128
#define OPAD 132
#define OUT3_FLOATS (64 * 64 + 64 * OPAD)
#define OUT3_BYTES  (OUT3_FLOATS * 4)

__global__ __launch_bounds__(256) void out3_kernel(float* __restrict__ out) {
    extern __shared__ float dsm[];
    float* sW = dsm;                 // [f][o]
    float* sVT = dsm + 64 * 64;      // [f][cl]

    int tid = threadIdx.x;
    int b = blockIdx.y;
    int m0 = blockIdx.x * OTILE;

    {
        float4* d4 = (float4*)sW;
        const float4* s4 = (const float4*)g_WovT;
        for (int i = tid; i < 1024; i += 256) d4[i] = s4[i];
    }
    // staging: 2 threads per row (2-way max conflicts)
    {
        int cl = tid >> 1;
        int half = tid & 1;
        int m = m0 + cl;
        const float4* src = (const float4*)(g_vbar + ((size_t)b * MR + m) * 64 + half * 32);
        bool ok = (m < MR);
#pragma unroll
        for (int k = 0; k < 8; k++) {
            float4 v = ok ? src[k] : make_float4(0.f, 0.f, 0.f, 0.f);
            int f = half * 32 + k * 4;
            sVT[(f + 0) * OPAD + cl] = v.x;
            sVT[(f + 1) * OPAD + cl] = v.y;
            sVT[(f + 2) * OPAD + cl] = v.z;
            sVT[(f + 3) * OPAD + cl] = v.w;
        }
    }
    __syncthreads();

    int warp = tid >> 5;
    int lane = tid & 31;
    int o0 = warp * 8;           // warp shares this o-group -> broadcast W reads
    int ml0 = lane * 4;          // lanes tile m

    ull acc2[4][4];   // p = o-pair (o0+2p, o0+2p+1), j = m offset
#pragma unroll
    for (int p = 0; p < 4; p++)
#pragma unroll
        for (int j = 0; j < 4; j++) acc2[p][j] = 0ull;

#pragma unroll 4
    for (int f = 0; f < 64; f++) {
        const float* wrow = sW + f * 64 + o0;   // uniform address across warp
        ull w2[4];
#pragma unroll
        for (int p = 0; p < 4; p++) w2[p] = *(const ull*)(wrow + 2 * p);  // natural pairs
        const float4 vv = *(const float4*)(sVT + f * OPAD + ml0);  // 16B aligned
        ull v2[4];
        asm("mov.b64 %0, {%1, %1};" : "=l"(v2[0]) : "f"(vv.x));
        asm("mov.b64 %0, {%1, %1};" : "=l"(v2[1]) : "f"(vv.y));
        asm("mov.b64 %0, {%1, %1};" : "=l"(v2[2]) : "f"(vv.z));
        asm("mov.b64 %0, {%1, %1};" : "=l"(v2[3]) : "f"(vv.w));
#pragma unroll
        for (int p = 0; p < 4; p++)
#pragma unroll
            for (int j = 0; j < 4; j++)
                asm("fma.rn.f32x2 %0, %1, %2, %0;"
                    : "+l"(acc2[p][j]) : "l"(w2[p]), "l"(v2[j]));
    }

    if (m0 + ml0 + 3 < MR) {      // MR % 4 == 0 -> all-or-nothing
        float a[8][4];            // [o_local][m_local]
#pragma unroll
        for (int p = 0; p < 4; p++)
#pragma unroll
            for (int j = 0; j < 4; j++)
                asm("mov.b64 {%0, %1}, %2;"
                    : "=f"(a[2 * p][j]), "=f"(a[2 * p + 1][j]) : "l"(acc2[p][j]));
#pragma unroll
        for (int ol = 0; ol < 8; ol++) {
            float* dst = out + ((size_t)b * CO + o0 + ol) * MR + m0 + ml0;
            *(float4*)dst = make_float4(a[ol][0], a[ol][1], a[ol][2], a[ol][3]);
        }
    }
}

// ---------------- launch ----------------
extern "C" void kernel_launch(void* const* d_in, const int* in_sizes, int n_in,
                              void* d_out, int out_size) {
    const float* v_feat = (const float*)d_in[0];
    const float* r_feat = (const float*)d_in[1];
    const float* Wq = (const float*)d_in[2];
    const float* Wk = (const float*)d_in[3];
    const float* Wv = (const float*)d_in[4];
    const float* Wo = (const float*)d_in[5];
    const void* v2p = d_in[6];
    const void* r2p = d_in[7];
    float* out = (float*)d_out;

    cudaFuncSetAttribute(out3_kernel, cudaFuncAttributeMaxDynamicSharedMemorySize,
                         OUT3_BYTES);

    // 1) phase1 (lean): vT transpose || repack || zero || weight folds
    phase1_kernel<<<P1_GRID, 256>>>(v_feat, v2p, r2p, Wq, Wk, Wv, Wo);

    // 2) dense q GEMM
    qd_kernel<<<dim3((MR + QD_TILE - 1) / QD_TILE, B_), 256>>>(r_feat);

    // 3) attention: batched gathers, softmax, RED into g_vbar
    attn_kernel<<<TOTN / 32, 256>>>();

    // 4) dense Wov GEMM (o-paired f32x2, no W-packing MOVs) + direct store
    out3_kernel<<<dim3((MR + OTILE - 1) / OTILE, B_), 256, OUT3_BYTES>>>(out);
}